// round 4
// baseline (speedup 1.0000x reference)
#include <cuda_runtime.h>
#include <cstdint>
#include <cstddef>

#define Bn 256
#define Tn 2048
#define Nn 17
#define En 8
#define An 4
#define Mn 2
#define Hn 768
#define FULL 0xffffffffu

__device__ float g_trans[Nn * Nn];
__device__ float g_E[Nn * Nn];
__device__ float g_scratch[Bn];
__device__ int g_done;

// ---------------------------------------------------------------------------
// Kernel 1: build transition matrix (17x17) and its elementwise exp.
// ---------------------------------------------------------------------------
__global__ void k_build(const float* __restrict__ hiddens,
                        const float* __restrict__ p_in,
                        const float* __restrict__ p_cross,
                        const float* __restrict__ p_out,
                        const float* __restrict__ p_to_out,
                        const float* __restrict__ p_from_out,
                        const float* __restrict__ w_attn,
                        const float* __restrict__ b_attn) {
    __shared__ float att[En][An];
    int tid = threadIdx.x;
    int wid = tid >> 5, lane = tid & 31;
    if (tid == 0) g_done = 0;
    if (wid < En * An) {
        int e = wid / An, a = wid % An;
        float s = 0.f;
        for (int h = lane; h < Hn; h += 32)
            s = fmaf(hiddens[e * Hn + h], w_attn[h * An + a], s);
#pragma unroll
        for (int off = 16; off; off >>= 1) s += __shfl_xor_sync(FULL, s, off);
        if (lane == 0) att[e][a] = s + b_attn[a];
    }
    __syncthreads();
    if (tid < An) {                  // softmax over e (axis 0)
        int a = tid;
        float col[En], mx = -3.4e38f;
        for (int e = 0; e < En; e++) { col[e] = att[e][a]; mx = fmaxf(mx, col[e]); }
        float sm = 0.f;
        for (int e = 0; e < En; e++) { col[e] = expf(col[e] - mx); sm += col[e]; }
        for (int e = 0; e < En; e++) att[e][a] = col[e] / sm;
    }
    __syncthreads();
    if (tid < En) {                  // softmax over a (axis -1) of att*10
        int e = tid;
        float row[An], mx = -3.4e38f;
        for (int a = 0; a < An; a++) { row[a] = att[e][a] * 10.f; mx = fmaxf(mx, row[a]); }
        float sm = 0.f;
        for (int a = 0; a < An; a++) { row[a] = expf(row[a] - mx); sm += row[a]; }
        for (int a = 0; a < An; a++) att[e][a] = row[a] / sm;
    }
    __syncthreads();
    if (tid < Nn * Nn) {
        int r = tid / Nn, c = tid % Nn;
        float v;
        if (r == 0 && c == 0) {
            v = p_out[0];
        } else if (r == 0) {
            v = p_from_out[(c - 1) % Mn];
        } else if (c == 0) {
            v = p_to_out[(r - 1) % Mn];
        } else {
            int e = (r - 1) / Mn, m = (r - 1) % Mn;
            int f = (c - 1) / Mn, mp = (c - 1) % Mn;
            if (e == f) {
                float s2 = 0.f;
                for (int a = 0; a < An; a++)
                    s2 = fmaf(p_in[a * Mn * Mn + m * Mn + mp], att[e][a], s2);
                v = s2 * (1.0f / An);
            } else {
                v = p_cross[m * Mn + mp];
            }
        }
        g_trans[tid] = v;
        g_E[tid] = expf(v);
    }
}

// ---------------------------------------------------------------------------
// Kernel 2: 3 warps per batch. warp0: forward scan t=[0,1023]. warp1:
// transposed backward scan t=[2047..1024]. warp2: numerator (no recursion).
// Per-step prefetch is spread (2 LDG + 1 expf per step) via 16-deep circular
// register buffers indexed t&15; renorm uses the already-loaded v0.x.
// ---------------------------------------------------------------------------
__global__ void __launch_bounds__(96)
k_scan(const float* __restrict__ inputs,
       const int* __restrict__ tags,
       const int* __restrict__ mask,
       float* __restrict__ out) {
    int b = blockIdx.x;
    int wid = threadIdx.x >> 5;
    int j = threadIdx.x & 31;
    bool act = (j < Nn);

    __shared__ float s_tr[Nn * Nn];
    __shared__ __align__(16) float wb[2][2][20];
    __shared__ float s_bvec[20];
    __shared__ double s_l2b;
    __shared__ float s_num;

    for (int idx = threadIdx.x; idx < Nn * Nn; idx += 96) s_tr[idx] = g_trans[idx];
    __syncthreads();

    const float* inp = inputs + (size_t)b * Tn * Nn;
    const int* tgp = tags + (size_t)b * Tn;
    const int* mkp = mask + (size_t)b * Tn;

    if (wid == 0) {
        // ===================== FORWARD: t in [0, 1023] =====================
        float E0  = act ? g_E[0 * Nn + j]  : 0.f, E1  = act ? g_E[1 * Nn + j]  : 0.f;
        float E2  = act ? g_E[2 * Nn + j]  : 0.f, E3  = act ? g_E[3 * Nn + j]  : 0.f;
        float E4  = act ? g_E[4 * Nn + j]  : 0.f, E5  = act ? g_E[5 * Nn + j]  : 0.f;
        float E6  = act ? g_E[6 * Nn + j]  : 0.f, E7  = act ? g_E[7 * Nn + j]  : 0.f;
        float E8  = act ? g_E[8 * Nn + j]  : 0.f, E9  = act ? g_E[9 * Nn + j]  : 0.f;
        float E10 = act ? g_E[10 * Nn + j] : 0.f, E11 = act ? g_E[11 * Nn + j] : 0.f;
        float E12 = act ? g_E[12 * Nn + j] : 0.f, E13 = act ? g_E[13 * Nn + j] : 0.f;
        float E14 = act ? g_E[14 * Nn + j] : 0.f, E15 = act ? g_E[15 * Nn + j] : 0.f;
        float E16 = act ? g_E[16 * Nn + j] : 0.f;

        float r[16]; int m[16]; float ew[16];
#pragma unroll
        for (int k = 0; k < 16; k++) {
            r[k] = act ? __ldg(inp + (size_t)k * Nn + j) : 0.f;
            m[k] = __ldg(mkp + k);
        }
#pragma unroll
        for (int k = 0; k <= 8; k++) ew[k] = __expf(r[k]);

        // t = 0 init
        float r0v = r[0];
        float s0 = __shfl_sync(FULL, r0v, 0);
        float w = act ? __expf(r0v - s0) : 0.f;
        double l2 = 0.0;
        r[0] = act ? __ldg(inp + (size_t)16 * Nn + j) : 0.f;
        m[0] = __ldg(mkp + 16);
        if (act) wb[0][0][j] = w;

#define FSTEP(S, TB) { \
        __syncwarp(); \
        float4 v0 = *(const float4*)&wb[0][((S) + 1) & 1][0]; \
        float4 v1 = *(const float4*)&wb[0][((S) + 1) & 1][4]; \
        float4 v2 = *(const float4*)&wb[0][((S) + 1) & 1][8]; \
        float4 v3 = *(const float4*)&wb[0][((S) + 1) & 1][12]; \
        float v16 = wb[0][((S) + 1) & 1][16]; \
        int mv = m[(S) & 15]; \
        m[(S) & 15] = __ldg(mkp + (TB) + (S) + 16); \
        r[(S) & 15] = act ? __ldg(inp + (size_t)((TB) + (S) + 16) * Nn + j) : 0.f; \
        ew[((S) + 8) & 15] = __expf(r[((S) + 8) & 15]); \
        float a0 = v0.x * E0, a1 = v0.y * E1, a2 = v0.z * E2, a3 = v0.w * E3; \
        float a4 = v1.x * E4, a5 = v1.y * E5, a6 = v1.z * E6, a7 = v1.w * E7; \
        a0 = fmaf(v2.x, E8, a0);  a1 = fmaf(v2.y, E9, a1); \
        a2 = fmaf(v2.z, E10, a2); a3 = fmaf(v2.w, E11, a3); \
        a4 = fmaf(v3.x, E12, a4); a5 = fmaf(v3.y, E13, a5); \
        a6 = fmaf(v3.z, E14, a6); a7 = fmaf(v3.w, E15, a7); \
        a0 = fmaf(v16, E16, a0); \
        float wn = ew[(S) & 15] * (((a0 + a1) + (a2 + a3)) + ((a4 + a5) + (a6 + a7))); \
        w = (mv > 0) ? wn : w; \
        if (((S) & 7) == 7) { float sc = v0.x; w *= __frcp_rn(sc); l2 += (double)__log2f(sc); } \
        if (act) wb[0][(S) & 1][j] = w; }

        // peel block 0: steps t = 1..15
#pragma unroll
        for (int s = 1; s < 16; s++) { FSTEP(s, 0) }
        // main blocks: t = 16..1023
        for (int tb = 16; tb < 1024; tb += 16) {
#pragma unroll
            for (int s = 0; s < 16; s++) { FSTEP(s, tb) }
        }
#undef FSTEP

        // ---- combine ----
        __syncthreads();
        float prod = act ? w * s_bvec[j] : 0.f;
#pragma unroll
        for (int off = 16; off; off >>= 1) prod += __shfl_xor_sync(FULL, prod, off);
        if (j == 0) {
            double den = (double)s0 + 0.6931471805599453 * (l2 + s_l2b)
                       + log((double)prod);
            g_scratch[b] = (float)((double)s_num - den);
            __threadfence();
        }
        int flag = 0;
        if (j == 0) {
            int ticket = atomicAdd(&g_done, 1);
            flag = (ticket == Bn - 1);
        }
        flag = __shfl_sync(FULL, flag, 0);
        if (flag) {
            __threadfence();
            volatile float* gs = g_scratch;
            double acc = 0.0;
#pragma unroll
            for (int k = 0; k < Bn / 32; k++) acc += (double)gs[j + k * 32];
#pragma unroll
            for (int off = 16; off; off >>= 1) acc += __shfl_xor_sync(FULL, acc, off);
            if (j == 0) out[0] = (float)acc;
        }
    } else if (wid == 1) {
        // ===================== BACKWARD: t in [2047 .. 1024] =====================
        float F0  = act ? g_E[j * Nn + 0]  : 0.f, F1  = act ? g_E[j * Nn + 1]  : 0.f;
        float F2  = act ? g_E[j * Nn + 2]  : 0.f, F3  = act ? g_E[j * Nn + 3]  : 0.f;
        float F4  = act ? g_E[j * Nn + 4]  : 0.f, F5  = act ? g_E[j * Nn + 5]  : 0.f;
        float F6  = act ? g_E[j * Nn + 6]  : 0.f, F7  = act ? g_E[j * Nn + 7]  : 0.f;
        float F8  = act ? g_E[j * Nn + 8]  : 0.f, F9  = act ? g_E[j * Nn + 9]  : 0.f;
        float F10 = act ? g_E[j * Nn + 10] : 0.f, F11 = act ? g_E[j * Nn + 11] : 0.f;
        float F12 = act ? g_E[j * Nn + 12] : 0.f, F13 = act ? g_E[j * Nn + 13] : 0.f;
        float F14 = act ? g_E[j * Nn + 14] : 0.f, F15 = act ? g_E[j * Nn + 15] : 0.f;
        float F16 = act ? g_E[j * Nn + 16] : 0.f;

        float r[16]; int m[16]; float ew[16];
#pragma unroll
        for (int k = 0; k < 16; k++) {
            int tt = 2032 + k;
            r[k] = act ? __ldg(inp + (size_t)tt * Nn + j) : 0.f;
            m[k] = __ldg(mkp + tt);
        }
#pragma unroll
        for (int k = 8; k < 16; k++) ew[k] = __expf(r[k]);

        float ur = 1.0f;
        double l2 = 0.0;

#define BSTEP(S, TB) { \
        float z = ew[(S) & 15] * ur; \
        if (act) wb[1][(S) & 1][j] = z; \
        __syncwarp(); \
        float4 v0 = *(const float4*)&wb[1][(S) & 1][0]; \
        float4 v1 = *(const float4*)&wb[1][(S) & 1][4]; \
        float4 v2 = *(const float4*)&wb[1][(S) & 1][8]; \
        float4 v3 = *(const float4*)&wb[1][(S) & 1][12]; \
        float v16 = wb[1][(S) & 1][16]; \
        int mv = m[(S) & 15]; \
        m[(S) & 15] = __ldg(mkp + (TB) + (S) - 16); \
        r[(S) & 15] = act ? __ldg(inp + (size_t)((TB) + (S) - 16) * Nn + j) : 0.f; \
        ew[((S) + 8) & 15] = __expf(r[((S) + 8) & 15]); \
        float a0 = v0.x * F0, a1 = v0.y * F1, a2 = v0.z * F2, a3 = v0.w * F3; \
        float a4 = v1.x * F4, a5 = v1.y * F5, a6 = v1.z * F6, a7 = v1.w * F7; \
        a0 = fmaf(v2.x, F8, a0);  a1 = fmaf(v2.y, F9, a1); \
        a2 = fmaf(v2.z, F10, a2); a3 = fmaf(v2.w, F11, a3); \
        a4 = fmaf(v3.x, F12, a4); a5 = fmaf(v3.y, F13, a5); \
        a6 = fmaf(v3.z, F14, a6); a7 = fmaf(v3.w, F15, a7); \
        a0 = fmaf(v16, F16, a0); \
        float cand = ((a0 + a1) + (a2 + a3)) + ((a4 + a5) + (a6 + a7)); \
        ur = (mv > 0) ? cand : ur; \
        if (((S) & 7) == 0) { float sc = v0.x; ur *= __frcp_rn(sc); l2 += (double)__log2f(sc); } }

        for (int tb = 2032; tb >= 1024; tb -= 16) {
#pragma unroll
            for (int s = 15; s >= 0; s--) { BSTEP(s, tb) }
        }
#undef BSTEP

        if (act) s_bvec[j] = ur;
        if (j == 0) s_l2b = l2;
        __syncthreads();
    } else {
        // ===================== NUMERATOR (no recursion) =====================
        float tr_acc = 0.f, em_acc = 0.f;
        int cnt = 0;
        for (int t = j; t < Tn - 1; t += 32) {
            int tg0 = __ldg(tgp + t), tg1 = __ldg(tgp + t + 1);
            int mk0 = __ldg(mkp + t), mk1 = __ldg(mkp + t + 1);
            float ev = __ldg(inp + (size_t)t * Nn + tg0);
            tr_acc = fmaf(s_tr[tg0 * Nn + tg1], (float)mk1, tr_acc);
            em_acc = fmaf(ev, (float)mk0, em_acc);
            cnt += mk0;
        }
#pragma unroll
        for (int off = 16; off; off >>= 1) {
            tr_acc += __shfl_xor_sync(FULL, tr_acc, off);
            em_acc += __shfl_xor_sync(FULL, em_acc, off);
            cnt += __shfl_xor_sync(FULL, cnt, off);
        }
        if (j == 0) {
            int mkL = __ldg(mkp + Tn - 1);
            cnt += mkL;
            int li = cnt - 1; if (li < 0) li = 0;
            int tagL = __ldg(tgp + li);
            float evL = __ldg(inp + (size_t)(Tn - 1) * Nn + tagL) * (float)mkL;
            s_num = tr_acc + em_acc + evL;
        }
        __syncthreads();
    }
}

extern "C" void kernel_launch(void* const* d_in, const int* in_sizes, int n_in,
                              void* d_out, int out_size) {
    const float* inputs     = (const float*)d_in[0];
    const int*   tags       = (const int*)d_in[1];
    const float* hiddens    = (const float*)d_in[2];
    const int*   mask       = (const int*)d_in[3];
    const float* p_in       = (const float*)d_in[4];
    const float* p_cross    = (const float*)d_in[5];
    const float* p_out      = (const float*)d_in[6];
    const float* p_to_out   = (const float*)d_in[7];
    const float* p_from_out = (const float*)d_in[8];
    const float* w_attn     = (const float*)d_in[9];
    const float* b_attn     = (const float*)d_in[10];

    k_build<<<1, 1024>>>(hiddens, p_in, p_cross, p_out, p_to_out, p_from_out,
                         w_attn, b_attn);
    k_scan<<<Bn, 96>>>(inputs, tags, mask, (float*)d_out);
}

// round 5
// speedup vs baseline: 1.3708x; 1.3708x over previous
#include <cuda_runtime.h>
#include <cstdint>
#include <cstddef>

#define Bn 256
#define Tn 2048
#define Nn 17
#define En 8
#define An 4
#define Mn 2
#define Hn 768
#define FULL 0xffffffffu

__device__ float g_trans[Nn * Nn];
__device__ float g_E[Nn * Nn];
__device__ float g_scratch[Bn];
__device__ int g_done;

// ---------------------------------------------------------------------------
// Kernel 1: build transition matrix (17x17) and its elementwise exp.
// ---------------------------------------------------------------------------
__global__ void k_build(const float* __restrict__ hiddens,
                        const float* __restrict__ p_in,
                        const float* __restrict__ p_cross,
                        const float* __restrict__ p_out,
                        const float* __restrict__ p_to_out,
                        const float* __restrict__ p_from_out,
                        const float* __restrict__ w_attn,
                        const float* __restrict__ b_attn) {
    __shared__ float att[En][An];
    int tid = threadIdx.x;
    int wid = tid >> 5, lane = tid & 31;
    if (tid == 0) g_done = 0;
    if (wid < En * An) {
        int e = wid / An, a = wid % An;
        float s = 0.f;
        for (int h = lane; h < Hn; h += 32)
            s = fmaf(hiddens[e * Hn + h], w_attn[h * An + a], s);
#pragma unroll
        for (int off = 16; off; off >>= 1) s += __shfl_xor_sync(FULL, s, off);
        if (lane == 0) att[e][a] = s + b_attn[a];
    }
    __syncthreads();
    if (tid < An) {                  // softmax over e (axis 0)
        int a = tid;
        float col[En], mx = -3.4e38f;
        for (int e = 0; e < En; e++) { col[e] = att[e][a]; mx = fmaxf(mx, col[e]); }
        float sm = 0.f;
        for (int e = 0; e < En; e++) { col[e] = expf(col[e] - mx); sm += col[e]; }
        for (int e = 0; e < En; e++) att[e][a] = col[e] / sm;
    }
    __syncthreads();
    if (tid < En) {                  // softmax over a (axis -1) of att*10
        int e = tid;
        float row[An], mx = -3.4e38f;
        for (int a = 0; a < An; a++) { row[a] = att[e][a] * 10.f; mx = fmaxf(mx, row[a]); }
        float sm = 0.f;
        for (int a = 0; a < An; a++) { row[a] = expf(row[a] - mx); sm += row[a]; }
        for (int a = 0; a < An; a++) att[e][a] = row[a] / sm;
    }
    __syncthreads();
    if (tid < Nn * Nn) {
        int r = tid / Nn, c = tid % Nn;
        float v;
        if (r == 0 && c == 0) {
            v = p_out[0];
        } else if (r == 0) {
            v = p_from_out[(c - 1) % Mn];
        } else if (c == 0) {
            v = p_to_out[(r - 1) % Mn];
        } else {
            int e = (r - 1) / Mn, m = (r - 1) % Mn;
            int f = (c - 1) / Mn, mp = (c - 1) % Mn;
            if (e == f) {
                float s2 = 0.f;
                for (int a = 0; a < An; a++)
                    s2 = fmaf(p_in[a * Mn * Mn + m * Mn + mp], att[e][a], s2);
                v = s2 * (1.0f / An);
            } else {
                v = p_cross[m * Mn + mp];
            }
        }
        g_trans[tid] = v;
        g_E[tid] = expf(v);
    }
}

// ---------------------------------------------------------------------------
// Kernel 2: 3 warps per batch. warp0: forward v <- diag(ew) E^T v, t=[0,1023].
// warp1: backward u <- E (ew .* u), t=[2047..1024]. warp2: numerator sums.
// den = log(u.v) + scales. Block-rotation prefetch (8-deep, register-resident),
// free renorm via prev-step w[0] (already loaded for the FMA tree).
// ---------------------------------------------------------------------------
__global__ void __launch_bounds__(96, 2)
k_scan(const float* __restrict__ inputs,
       const int* __restrict__ tags,
       const int* __restrict__ mask,
       float* __restrict__ out) {
    int b = blockIdx.x;
    int wid = threadIdx.x >> 5;
    int j = threadIdx.x & 31;
    bool act = (j < Nn);

    __shared__ float s_tr[Nn * Nn];
    __shared__ __align__(16) float wb[2][2][20];
    __shared__ float s_bvec[20];
    __shared__ double s_l2b;
    __shared__ float s_num;

    for (int idx = threadIdx.x; idx < Nn * Nn; idx += 96) s_tr[idx] = g_trans[idx];
    __syncthreads();

    const float* inp = inputs + (size_t)b * Tn * Nn;
    const int* tgp = tags + (size_t)b * Tn;
    const int* mkp = mask + (size_t)b * Tn;

    if (wid == 0) {
        // ===================== FORWARD: t in [0, 1023] =====================
        float E0  = act ? g_E[0 * Nn + j]  : 0.f, E1  = act ? g_E[1 * Nn + j]  : 0.f;
        float E2  = act ? g_E[2 * Nn + j]  : 0.f, E3  = act ? g_E[3 * Nn + j]  : 0.f;
        float E4  = act ? g_E[4 * Nn + j]  : 0.f, E5  = act ? g_E[5 * Nn + j]  : 0.f;
        float E6  = act ? g_E[6 * Nn + j]  : 0.f, E7  = act ? g_E[7 * Nn + j]  : 0.f;
        float E8  = act ? g_E[8 * Nn + j]  : 0.f, E9  = act ? g_E[9 * Nn + j]  : 0.f;
        float E10 = act ? g_E[10 * Nn + j] : 0.f, E11 = act ? g_E[11 * Nn + j] : 0.f;
        float E12 = act ? g_E[12 * Nn + j] : 0.f, E13 = act ? g_E[13 * Nn + j] : 0.f;
        float E14 = act ? g_E[14 * Nn + j] : 0.f, E15 = act ? g_E[15 * Nn + j] : 0.f;
        float E16 = act ? g_E[16 * Nn + j] : 0.f;

        float rA[8], rB[8], rC[8];
        int mA[8], mB[8], mC[8];
        float ew[8];
#pragma unroll
        for (int u = 0; u < 8; u++) {
            rA[u] = act ? __ldg(inp + (size_t)u * Nn + j) : 0.f;
            mA[u] = __ldg(mkp + u);
            rB[u] = act ? __ldg(inp + (size_t)(8 + u) * Nn + j) : 0.f;
            mB[u] = __ldg(mkp + 8 + u);
            rC[u] = 0.f; mC[u] = 0;
        }
#pragma unroll
        for (int u = 0; u < 8; u++) ew[u] = __expf(rA[u]);

        float r0v = rA[0];
        float s0 = __shfl_sync(FULL, r0v, 0);
        float w = act ? __expf(r0v - s0) : 0.f;
        double l2 = 0.0;
        if (act) wb[0][0][j] = w;

        for (int blk = 0; blk < 128; blk++) {
            if (blk + 2 < 128) {
                int tp = (blk + 2) * 8;
#pragma unroll
                for (int u = 0; u < 8; u++) {
                    rC[u] = act ? __ldg(inp + (size_t)(tp + u) * Nn + j) : 0.f;
                    mC[u] = __ldg(mkp + tp + u);
                }
            }
#pragma unroll
            for (int u = 0; u < 8; u++) {
                if (blk == 0 && u == 0) continue;   // t=0 done in init
                __syncwarp();
                float4 v0 = *(const float4*)&wb[0][(u + 1) & 1][0];
                float4 v1 = *(const float4*)&wb[0][(u + 1) & 1][4];
                float4 v2 = *(const float4*)&wb[0][(u + 1) & 1][8];
                float4 v3 = *(const float4*)&wb[0][(u + 1) & 1][12];
                float v16 = wb[0][(u + 1) & 1][16];
                float a0 = v0.x * E0, a1 = v0.y * E1, a2 = v0.z * E2, a3 = v0.w * E3;
                float a4 = v1.x * E4, a5 = v1.y * E5, a6 = v1.z * E6, a7 = v1.w * E7;
                a0 = fmaf(v2.x, E8, a0);  a1 = fmaf(v2.y, E9, a1);
                a2 = fmaf(v2.z, E10, a2); a3 = fmaf(v2.w, E11, a3);
                a4 = fmaf(v3.x, E12, a4); a5 = fmaf(v3.y, E13, a5);
                a6 = fmaf(v3.z, E14, a6); a7 = fmaf(v3.w, E15, a7);
                a0 = fmaf(v16, E16, a0);
                float wn = ew[u] * (((a0 + a1) + (a2 + a3)) + ((a4 + a5) + (a6 + a7)));
                w = (mA[u] > 0) ? wn : w;
                if (u == 7) {   // free renorm: v0.x = prev step's w[0]
                    float sc = v0.x;
                    w *= __frcp_rn(sc);
                    l2 += (double)__log2f(sc);
                }
                if (act) wb[0][u & 1][j] = w;
            }
#pragma unroll
            for (int u = 0; u < 8; u++) {
                ew[u] = __expf(rB[u]);
                rA[u] = rB[u]; mA[u] = mB[u];
                rB[u] = rC[u]; mB[u] = mC[u];
            }
        }

        // ---- combine ----
        __syncthreads();
        float prod = act ? w * s_bvec[j] : 0.f;
#pragma unroll
        for (int off = 16; off; off >>= 1) prod += __shfl_xor_sync(FULL, prod, off);
        if (j == 0) {
            double den = (double)s0 + 0.6931471805599453 * (l2 + s_l2b)
                       + log((double)prod);
            g_scratch[b] = (float)((double)s_num - den);
            __threadfence();
        }
        int flag = 0;
        if (j == 0) {
            int ticket = atomicAdd(&g_done, 1);
            flag = (ticket == Bn - 1);
        }
        flag = __shfl_sync(FULL, flag, 0);
        if (flag) {
            __threadfence();
            volatile float* gs = g_scratch;
            double acc = 0.0;
#pragma unroll
            for (int k = 0; k < Bn / 32; k++) acc += (double)gs[j + k * 32];
#pragma unroll
            for (int off = 16; off; off >>= 1) acc += __shfl_xor_sync(FULL, acc, off);
            if (j == 0) out[0] = (float)acc;
        }
    } else if (wid == 1) {
        // ===================== BACKWARD: t in [2047 .. 1024] =====================
        float F0  = act ? g_E[j * Nn + 0]  : 0.f, F1  = act ? g_E[j * Nn + 1]  : 0.f;
        float F2  = act ? g_E[j * Nn + 2]  : 0.f, F3  = act ? g_E[j * Nn + 3]  : 0.f;
        float F4  = act ? g_E[j * Nn + 4]  : 0.f, F5  = act ? g_E[j * Nn + 5]  : 0.f;
        float F6  = act ? g_E[j * Nn + 6]  : 0.f, F7  = act ? g_E[j * Nn + 7]  : 0.f;
        float F8  = act ? g_E[j * Nn + 8]  : 0.f, F9  = act ? g_E[j * Nn + 9]  : 0.f;
        float F10 = act ? g_E[j * Nn + 10] : 0.f, F11 = act ? g_E[j * Nn + 11] : 0.f;
        float F12 = act ? g_E[j * Nn + 12] : 0.f, F13 = act ? g_E[j * Nn + 13] : 0.f;
        float F14 = act ? g_E[j * Nn + 14] : 0.f, F15 = act ? g_E[j * Nn + 15] : 0.f;
        float F16 = act ? g_E[j * Nn + 16] : 0.f;

        float rA[8], rB[8], rC[8];
        int mA[8], mB[8], mC[8];
        float ew[8];
#pragma unroll
        for (int u = 0; u < 8; u++) {
            rA[u] = act ? __ldg(inp + (size_t)(2040 + u) * Nn + j) : 0.f;
            mA[u] = __ldg(mkp + 2040 + u);
            rB[u] = act ? __ldg(inp + (size_t)(2032 + u) * Nn + j) : 0.f;
            mB[u] = __ldg(mkp + 2032 + u);
            rC[u] = 0.f; mC[u] = 0;
        }
#pragma unroll
        for (int u = 0; u < 8; u++) ew[u] = __expf(rA[u]);

        float ur = 1.0f;
        double l2 = 0.0;

        for (int tb = 2040; tb >= 1024; tb -= 8) {
            if (tb - 16 >= 1024) {
                int tp = tb - 16;
#pragma unroll
                for (int u = 0; u < 8; u++) {
                    rC[u] = act ? __ldg(inp + (size_t)(tp + u) * Nn + j) : 0.f;
                    mC[u] = __ldg(mkp + tp + u);
                }
            }
#pragma unroll
            for (int u = 7; u >= 0; u--) {
                float z = ew[u] * ur;
                if (act) wb[1][u & 1][j] = z;
                __syncwarp();
                float4 v0 = *(const float4*)&wb[1][u & 1][0];
                float4 v1 = *(const float4*)&wb[1][u & 1][4];
                float4 v2 = *(const float4*)&wb[1][u & 1][8];
                float4 v3 = *(const float4*)&wb[1][u & 1][12];
                float v16 = wb[1][u & 1][16];
                float a0 = v0.x * F0, a1 = v0.y * F1, a2 = v0.z * F2, a3 = v0.w * F3;
                float a4 = v1.x * F4, a5 = v1.y * F5, a6 = v1.z * F6, a7 = v1.w * F7;
                a0 = fmaf(v2.x, F8, a0);  a1 = fmaf(v2.y, F9, a1);
                a2 = fmaf(v2.z, F10, a2); a3 = fmaf(v2.w, F11, a3);
                a4 = fmaf(v3.x, F12, a4); a5 = fmaf(v3.y, F13, a5);
                a6 = fmaf(v3.z, F14, a6); a7 = fmaf(v3.w, F15, a7);
                a0 = fmaf(v16, F16, a0);
                float cand = ((a0 + a1) + (a2 + a3)) + ((a4 + a5) + (a6 + a7));
                ur = (mA[u] > 0) ? cand : ur;
                if (u == 0) {   // free renorm: v0.x = this step's z[0]
                    float sc = v0.x;
                    ur *= __frcp_rn(sc);
                    l2 += (double)__log2f(sc);
                }
            }
#pragma unroll
            for (int u = 0; u < 8; u++) {
                ew[u] = __expf(rB[u]);
                rA[u] = rB[u]; mA[u] = mB[u];
                rB[u] = rC[u]; mB[u] = mC[u];
            }
        }

        if (act) s_bvec[j] = ur;
        if (j == 0) s_l2b = l2;
        __syncthreads();
    } else {
        // ===================== NUMERATOR (no recursion) =====================
        float tr_acc = 0.f, em_acc = 0.f;
        int cnt = 0;
        for (int t = j; t < Tn - 1; t += 32) {
            int tg0 = __ldg(tgp + t), tg1 = __ldg(tgp + t + 1);
            int mk0 = __ldg(mkp + t), mk1 = __ldg(mkp + t + 1);
            float ev = __ldg(inp + (size_t)t * Nn + tg0);
            tr_acc = fmaf(s_tr[tg0 * Nn + tg1], (float)mk1, tr_acc);
            em_acc = fmaf(ev, (float)mk0, em_acc);
            cnt += mk0;
        }
#pragma unroll
        for (int off = 16; off; off >>= 1) {
            tr_acc += __shfl_xor_sync(FULL, tr_acc, off);
            em_acc += __shfl_xor_sync(FULL, em_acc, off);
            cnt += __shfl_xor_sync(FULL, cnt, off);
        }
        if (j == 0) {
            int mkL = __ldg(mkp + Tn - 1);
            cnt += mkL;
            int li = cnt - 1; if (li < 0) li = 0;
            int tagL = __ldg(tgp + li);
            float evL = __ldg(inp + (size_t)(Tn - 1) * Nn + tagL) * (float)mkL;
            s_num = tr_acc + em_acc + evL;
        }
        __syncthreads();
    }
}

extern "C" void kernel_launch(void* const* d_in, const int* in_sizes, int n_in,
                              void* d_out, int out_size) {
    const float* inputs     = (const float*)d_in[0];
    const int*   tags       = (const int*)d_in[1];
    const float* hiddens    = (const float*)d_in[2];
    const int*   mask       = (const int*)d_in[3];
    const float* p_in       = (const float*)d_in[4];
    const float* p_cross    = (const float*)d_in[5];
    const float* p_out      = (const float*)d_in[6];
    const float* p_to_out   = (const float*)d_in[7];
    const float* p_from_out = (const float*)d_in[8];
    const float* w_attn     = (const float*)d_in[9];
    const float* b_attn     = (const float*)d_in[10];

    k_build<<<1, 1024>>>(hiddens, p_in, p_cross, p_out, p_to_out, p_from_out,
                         w_attn, b_attn);
    k_scan<<<Bn, 96>>>(inputs, tags, mask, (float*)d_out);
}

// round 6
// speedup vs baseline: 1.3735x; 1.0020x over previous
#include <cuda_runtime.h>
#include <cstdint>
#include <cstddef>

#define Bn 256
#define Tn 2048
#define Nn 17
#define En 8
#define An 4
#define Mn 2
#define Hn 768
#define FULL 0xffffffffu

// segment lengths: fwd covers transitions t=1..575 (state after t=575),
// matrix B: t=576..1023, matrix C: t=1024..1471, bwd: t=1472..2047.
#define LV 576
#define LM 448
#define CH 32            // ring chunk (steps)
#define NCH (LM / CH)    // 14

__device__ float g_trans[Nn * Nn];
__device__ float g_E[Nn * Nn];
__device__ float g_scratch[Bn];
__device__ int g_done;

// ---------------------------------------------------------------------------
// Kernel 1: build transition matrix (17x17) and its elementwise exp.
// ---------------------------------------------------------------------------
__global__ void k_build(const float* __restrict__ hiddens,
                        const float* __restrict__ p_in,
                        const float* __restrict__ p_cross,
                        const float* __restrict__ p_out,
                        const float* __restrict__ p_to_out,
                        const float* __restrict__ p_from_out,
                        const float* __restrict__ w_attn,
                        const float* __restrict__ b_attn) {
    __shared__ float att[En][An];
    int tid = threadIdx.x;
    int wid = tid >> 5, lane = tid & 31;
    if (tid == 0) g_done = 0;
    if (wid < En * An) {
        int e = wid / An, a = wid % An;
        float s = 0.f;
        for (int h = lane; h < Hn; h += 32)
            s = fmaf(hiddens[e * Hn + h], w_attn[h * An + a], s);
#pragma unroll
        for (int off = 16; off; off >>= 1) s += __shfl_xor_sync(FULL, s, off);
        if (lane == 0) att[e][a] = s + b_attn[a];
    }
    __syncthreads();
    if (tid < An) {
        int a = tid;
        float col[En], mx = -3.4e38f;
        for (int e = 0; e < En; e++) { col[e] = att[e][a]; mx = fmaxf(mx, col[e]); }
        float sm = 0.f;
        for (int e = 0; e < En; e++) { col[e] = expf(col[e] - mx); sm += col[e]; }
        for (int e = 0; e < En; e++) att[e][a] = col[e] / sm;
    }
    __syncthreads();
    if (tid < En) {
        int e = tid;
        float row[An], mx = -3.4e38f;
        for (int a = 0; a < An; a++) { row[a] = att[e][a] * 10.f; mx = fmaxf(mx, row[a]); }
        float sm = 0.f;
        for (int a = 0; a < An; a++) { row[a] = expf(row[a] - mx); sm += row[a]; }
        for (int a = 0; a < An; a++) att[e][a] = row[a] / sm;
    }
    __syncthreads();
    if (tid < Nn * Nn) {
        int r = tid / Nn, c = tid % Nn;
        float v;
        if (r == 0 && c == 0) {
            v = p_out[0];
        } else if (r == 0) {
            v = p_from_out[(c - 1) % Mn];
        } else if (c == 0) {
            v = p_to_out[(r - 1) % Mn];
        } else {
            int e = (r - 1) / Mn, m = (r - 1) % Mn;
            int f = (c - 1) / Mn, mp = (c - 1) % Mn;
            if (e == f) {
                float s2 = 0.f;
                for (int a = 0; a < An; a++)
                    s2 = fmaf(p_in[a * Mn * Mn + m * Mn + mp], att[e][a], s2);
                v = s2 * (1.0f / An);
            } else {
                v = p_cross[m * Mn + mp];
            }
        }
        g_trans[tid] = v;
        g_E[tid] = expf(v);
    }
}

// ---------------------------------------------------------------------------
// Kernel 2: 5 warps per batch.
//  w0: forward vector scan  t = 1..LV-1       (latency-bound chain)
//  w1: backward vector scan t = 2047..2048-LV (latency-bound chain)
//  w2: matrix segment B     t = LV..LV+LM-1   (column-per-lane, no sync)
//  w3: matrix segment C     t = LV+LM..       (column-per-lane, no sync)
//  w4: producer (exp of emits into smem rings for w2/w3) + numerator
// den = log( y^T C_mat B_mat x ) + scales.
// ---------------------------------------------------------------------------
__global__ void __launch_bounds__(160, 2)
k_scan(const float* __restrict__ inputs,
       const int* __restrict__ tags,
       const int* __restrict__ mask,
       float* __restrict__ out) {
    int b = blockIdx.x;
    int wid = threadIdx.x >> 5;
    int j = threadIdx.x & 31;
    bool act = (j < Nn);

    __shared__ float s_tr[Nn * Nn];
    __shared__ __align__(16) float wb[2][2][20];
    __shared__ __align__(16) float ring[2][2][CH][20];   // [mid][slot][step][state/mask]
    __shared__ __align__(16) float smM[2][Nn][20];       // matrix columns
    __shared__ double smL[2][Nn];                        // matrix column log2-scales
    __shared__ __align__(16) float sx[20], sy[20], sxs[20], szz[20], szs[20];
    __shared__ double s_l2b;
    __shared__ float s_num;

    for (int idx = threadIdx.x; idx < Nn * Nn; idx += 160) s_tr[idx] = g_trans[idx];
    __syncthreads();

    const float* inp = inputs + (size_t)b * Tn * Nn;
    const int* tgp = tags + (size_t)b * Tn;
    const int* mkp = mask + (size_t)b * Tn;

    if (wid == 0) {
        // ===================== FORWARD: t in [0, LV) =====================
        float E0  = act ? g_E[0 * Nn + j]  : 0.f, E1  = act ? g_E[1 * Nn + j]  : 0.f;
        float E2  = act ? g_E[2 * Nn + j]  : 0.f, E3  = act ? g_E[3 * Nn + j]  : 0.f;
        float E4  = act ? g_E[4 * Nn + j]  : 0.f, E5  = act ? g_E[5 * Nn + j]  : 0.f;
        float E6  = act ? g_E[6 * Nn + j]  : 0.f, E7  = act ? g_E[7 * Nn + j]  : 0.f;
        float E8  = act ? g_E[8 * Nn + j]  : 0.f, E9  = act ? g_E[9 * Nn + j]  : 0.f;
        float E10 = act ? g_E[10 * Nn + j] : 0.f, E11 = act ? g_E[11 * Nn + j] : 0.f;
        float E12 = act ? g_E[12 * Nn + j] : 0.f, E13 = act ? g_E[13 * Nn + j] : 0.f;
        float E14 = act ? g_E[14 * Nn + j] : 0.f, E15 = act ? g_E[15 * Nn + j] : 0.f;
        float E16 = act ? g_E[16 * Nn + j] : 0.f;

        float rA[8], rB[8], rC[8];
        int mA[8], mB[8], mC[8];
        float ew[8];
#pragma unroll
        for (int u = 0; u < 8; u++) {
            rA[u] = act ? __ldg(inp + (size_t)u * Nn + j) : 0.f;
            mA[u] = __ldg(mkp + u);
            rB[u] = act ? __ldg(inp + (size_t)(8 + u) * Nn + j) : 0.f;
            mB[u] = __ldg(mkp + 8 + u);
            rC[u] = 0.f; mC[u] = 0;
        }
#pragma unroll
        for (int u = 0; u < 8; u++) ew[u] = __expf(rA[u]);

        float r0v = rA[0];
        float s0 = __shfl_sync(FULL, r0v, 0);
        float w = act ? __expf(r0v - s0) : 0.f;
        double l2 = 0.0;
        if (act) wb[0][0][j] = w;

        for (int blk = 0; blk < LV / 8; blk++) {
            if (blk + 2 < LV / 8) {
                int tp = (blk + 2) * 8;
#pragma unroll
                for (int u = 0; u < 8; u++) {
                    rC[u] = act ? __ldg(inp + (size_t)(tp + u) * Nn + j) : 0.f;
                    mC[u] = __ldg(mkp + tp + u);
                }
            }
#pragma unroll
            for (int u = 0; u < 8; u++) {
                if (blk == 0 && u == 0) continue;
                __syncwarp();
                float4 v0 = *(const float4*)&wb[0][(u + 1) & 1][0];
                float4 v1 = *(const float4*)&wb[0][(u + 1) & 1][4];
                float4 v2 = *(const float4*)&wb[0][(u + 1) & 1][8];
                float4 v3 = *(const float4*)&wb[0][(u + 1) & 1][12];
                float v16 = wb[0][(u + 1) & 1][16];
                float a0 = v0.x * E0, a1 = v0.y * E1, a2 = v0.z * E2, a3 = v0.w * E3;
                float a4 = v1.x * E4, a5 = v1.y * E5, a6 = v1.z * E6, a7 = v1.w * E7;
                a0 = fmaf(v2.x, E8, a0);  a1 = fmaf(v2.y, E9, a1);
                a2 = fmaf(v2.z, E10, a2); a3 = fmaf(v2.w, E11, a3);
                a4 = fmaf(v3.x, E12, a4); a5 = fmaf(v3.y, E13, a5);
                a6 = fmaf(v3.z, E14, a6); a7 = fmaf(v3.w, E15, a7);
                a0 = fmaf(v16, E16, a0);
                float wn = ew[u] * (((a0 + a1) + (a2 + a3)) + ((a4 + a5) + (a6 + a7)));
                w = (mA[u] > 0) ? wn : w;
                if (u == 7) {
                    float sc = v0.x;
                    w *= __frcp_rn(sc);
                    l2 += (double)__log2f(sc);
                }
                if (act) wb[0][u & 1][j] = w;
            }
#pragma unroll
            for (int u = 0; u < 8; u++) {
                ew[u] = __expf(rB[u]);
                rA[u] = rB[u]; mA[u] = mB[u];
                rB[u] = rC[u]; mB[u] = mC[u];
            }
        }
        if (act) sx[j] = w;
        __syncthreads();   // join

        // ---- combine: den = s0 + ln2*(l2f + l2b + maxB + maxC) + ln(y.(C.(B.x))) ----
        double maxB = -1e300, maxC = -1e300;
#pragma unroll
        for (int k = 0; k < Nn; k++) {
            double vB = smL[0][k], vC = smL[1][k];
            maxB = vB > maxB ? vB : maxB;
            maxC = vC > maxC ? vC : maxC;
        }
        if (act) sxs[j] = sx[j] * exp2f((float)(smL[0][j] - maxB));
        __syncwarp();
        float z = 0.f;
        if (act) {
#pragma unroll
            for (int k = 0; k < Nn; k++) z = fmaf(smM[0][k][j], sxs[k], z);
            szz[j] = z;
        }
        __syncwarp();
        if (act) szs[j] = szz[j] * exp2f((float)(smL[1][j] - maxC));
        __syncwarp();
        float z2 = 0.f;
        if (act) {
#pragma unroll
            for (int k = 0; k < Nn; k++) z2 = fmaf(smM[1][k][j], szs[k], z2);
        }
        float prod = act ? sy[j] * z2 : 0.f;
#pragma unroll
        for (int off = 16; off; off >>= 1) prod += __shfl_xor_sync(FULL, prod, off);
        if (j == 0) {
            double den = (double)s0
                       + 0.6931471805599453 * (l2 + s_l2b + maxB + maxC)
                       + log((double)prod);
            g_scratch[b] = (float)((double)s_num - den);
            __threadfence();
        }
        int flag = 0;
        if (j == 0) {
            int ticket = atomicAdd(&g_done, 1);
            flag = (ticket == Bn - 1);
        }
        flag = __shfl_sync(FULL, flag, 0);
        if (flag) {
            __threadfence();
            volatile float* gs = g_scratch;
            double acc = 0.0;
#pragma unroll
            for (int k = 0; k < Bn / 32; k++) acc += (double)gs[j + k * 32];
#pragma unroll
            for (int off = 16; off; off >>= 1) acc += __shfl_xor_sync(FULL, acc, off);
            if (j == 0) out[0] = (float)acc;
        }
    } else if (wid == 1) {
        // ===================== BACKWARD: t in [2048-LV, 2048) =====================
        float F0  = act ? g_E[j * Nn + 0]  : 0.f, F1  = act ? g_E[j * Nn + 1]  : 0.f;
        float F2  = act ? g_E[j * Nn + 2]  : 0.f, F3  = act ? g_E[j * Nn + 3]  : 0.f;
        float F4  = act ? g_E[j * Nn + 4]  : 0.f, F5  = act ? g_E[j * Nn + 5]  : 0.f;
        float F6  = act ? g_E[j * Nn + 6]  : 0.f, F7  = act ? g_E[j * Nn + 7]  : 0.f;
        float F8  = act ? g_E[j * Nn + 8]  : 0.f, F9  = act ? g_E[j * Nn + 9]  : 0.f;
        float F10 = act ? g_E[j * Nn + 10] : 0.f, F11 = act ? g_E[j * Nn + 11] : 0.f;
        float F12 = act ? g_E[j * Nn + 12] : 0.f, F13 = act ? g_E[j * Nn + 13] : 0.f;
        float F14 = act ? g_E[j * Nn + 14] : 0.f, F15 = act ? g_E[j * Nn + 15] : 0.f;
        float F16 = act ? g_E[j * Nn + 16] : 0.f;

        float rA[8], rB[8], rC[8];
        int mA[8], mB[8], mC[8];
        float ew[8];
#pragma unroll
        for (int u = 0; u < 8; u++) {
            rA[u] = act ? __ldg(inp + (size_t)(2040 + u) * Nn + j) : 0.f;
            mA[u] = __ldg(mkp + 2040 + u);
            rB[u] = act ? __ldg(inp + (size_t)(2032 + u) * Nn + j) : 0.f;
            mB[u] = __ldg(mkp + 2032 + u);
            rC[u] = 0.f; mC[u] = 0;
        }
#pragma unroll
        for (int u = 0; u < 8; u++) ew[u] = __expf(rA[u]);

        float ur = 1.0f;
        double l2 = 0.0;

        for (int tb = 2040; tb >= Tn - LV; tb -= 8) {
            if (tb - 16 >= Tn - LV) {
                int tp = tb - 16;
#pragma unroll
                for (int u = 0; u < 8; u++) {
                    rC[u] = act ? __ldg(inp + (size_t)(tp + u) * Nn + j) : 0.f;
                    mC[u] = __ldg(mkp + tp + u);
                }
            }
#pragma unroll
            for (int u = 7; u >= 0; u--) {
                float z = ew[u] * ur;
                if (act) wb[1][u & 1][j] = z;
                __syncwarp();
                float4 v0 = *(const float4*)&wb[1][u & 1][0];
                float4 v1 = *(const float4*)&wb[1][u & 1][4];
                float4 v2 = *(const float4*)&wb[1][u & 1][8];
                float4 v3 = *(const float4*)&wb[1][u & 1][12];
                float v16 = wb[1][u & 1][16];
                float a0 = v0.x * F0, a1 = v0.y * F1, a2 = v0.z * F2, a3 = v0.w * F3;
                float a4 = v1.x * F4, a5 = v1.y * F5, a6 = v1.z * F6, a7 = v1.w * F7;
                a0 = fmaf(v2.x, F8, a0);  a1 = fmaf(v2.y, F9, a1);
                a2 = fmaf(v2.z, F10, a2); a3 = fmaf(v2.w, F11, a3);
                a4 = fmaf(v3.x, F12, a4); a5 = fmaf(v3.y, F13, a5);
                a6 = fmaf(v3.z, F14, a6); a7 = fmaf(v3.w, F15, a7);
                a0 = fmaf(v16, F16, a0);
                float cand = ((a0 + a1) + (a2 + a3)) + ((a4 + a5) + (a6 + a7));
                ur = (mA[u] > 0) ? cand : ur;
                if (u == 0) {
                    float sc = v0.x;
                    ur *= __frcp_rn(sc);
                    l2 += (double)__log2f(sc);
                }
            }
#pragma unroll
            for (int u = 0; u < 8; u++) {
                ew[u] = __expf(rB[u]);
                rA[u] = rB[u]; mA[u] = mB[u];
                rB[u] = rC[u]; mB[u] = mC[u];
            }
        }
        if (act) sy[j] = ur;
        if (j == 0) s_l2b = l2;
        __syncthreads();   // join
    } else if (wid == 2 || wid == 3) {
        // ===================== MATRIX segment (column per lane) =====================
        int mid = wid - 2;
        // structured coefficients from g_E
        float EO = g_E[0], FO0 = g_E[1], FO1 = g_E[2];
        float TO0 = g_E[Nn], TO1 = g_E[2 * Nn];
        float C00 = g_E[1 * Nn + 3], C01 = g_E[1 * Nn + 4];
        float C10 = g_E[2 * Nn + 3], C11 = g_E[2 * Nn + 4];
        float D00[8], D01[8], D10[8], D11[8];
#pragma unroll
        for (int f = 0; f < 8; f++) {
            int r0 = (1 + 2 * f) * Nn, r1 = (2 + 2 * f) * Nn;
            int c0 = 1 + 2 * f, c1 = 2 + 2 * f;
            D00[f] = g_E[r0 + c0] - C00;
            D01[f] = g_E[r0 + c1] - C01;
            D10[f] = g_E[r1 + c0] - C10;
            D11[f] = g_E[r1 + c1] - C11;
        }
        float bb[17];
#pragma unroll
        for (int i = 0; i < 17; i++) bb[i] = (i == j) ? 1.f : 0.f;
        double l2 = 0.0;
        int scount = 0;

        for (int c = 0; c < NCH; c++) {
            asm volatile("bar.sync %0, %1;" :: "r"(1 + mid), "r"(64));
            const float* rbase = &ring[mid][c & 1][0][0];
#pragma unroll 4
            for (int s = 0; s < CH; s++) {
                const float* rw = rbase + s * 20;
                float4 e0 = *(const float4*)(rw + 0);
                float4 e1 = *(const float4*)(rw + 4);
                float4 e2 = *(const float4*)(rw + 8);
                float4 e3 = *(const float4*)(rw + 12);
                float2 et = *(const float2*)(rw + 16);
                float ee[17] = {e0.x, e0.y, e0.z, e0.w, e1.x, e1.y, e1.z, e1.w,
                                e2.x, e2.y, e2.z, e2.w, e3.x, e3.y, e3.z, e3.w, et.x};
                if (et.y > 0.f) {
                    float S0 = ((bb[1] + bb[3]) + (bb[5] + bb[7]))
                             + ((bb[9] + bb[11]) + (bb[13] + bb[15]));
                    float S1 = ((bb[2] + bb[4]) + (bb[6] + bb[8]))
                             + ((bb[10] + bb[12]) + (bb[14] + bb[16]));
                    float U0 = fmaf(C10, S1, C00 * S0);
                    float U1 = fmaf(C11, S1, C01 * S0);
                    float V0 = fmaf(FO0, bb[0], U0);
                    float V1 = fmaf(FO1, bb[0], U1);
                    float nb0 = fmaf(TO1, S1, fmaf(TO0, S0, EO * bb[0]));
                    bb[0] = ee[0] * nb0;
#pragma unroll
                    for (int f = 0; f < 8; f++) {
                        float bm0 = bb[1 + 2 * f], bm1 = bb[2 + 2 * f];
                        float t0 = fmaf(D10[f], bm1, fmaf(D00[f], bm0, V0));
                        float t1 = fmaf(D11[f], bm1, fmaf(D01[f], bm0, V1));
                        bb[1 + 2 * f] = ee[1 + 2 * f] * t0;
                        bb[2 + 2 * f] = ee[2 + 2 * f] * t1;
                    }
                }
                if ((++scount & 7) == 0) {
                    float sc = bb[0];
                    if (sc > 0.f) {
                        float iv = __frcp_rn(sc);
                        l2 += (double)__log2f(sc);
#pragma unroll
                        for (int i = 0; i < 17; i++) bb[i] *= iv;
                    }
                }
            }
        }
        if (act) {
#pragma unroll
            for (int i = 0; i < 17; i++) smM[mid][j][i] = bb[i];
            smL[mid][j] = l2;
        }
        __syncthreads();   // join
    } else {
        // ===================== PRODUCER + NUMERATOR =====================
        float tr_acc = 0.f, em_acc = 0.f;
        int cnt = 0;
        int nt = j;
        for (int c = 0; c < NCH; c++) {
#pragma unroll
            for (int mid = 0; mid < 2; mid++) {
                int t0 = LV + mid * LM + c * CH;
                if (j < Nn) {
#pragma unroll 8
                    for (int s = 0; s < CH; s++)
                        ring[mid][c & 1][s][j] =
                            __expf(__ldg(inp + (size_t)(t0 + s) * Nn + j));
                } else if (j == Nn) {
#pragma unroll 8
                    for (int s = 0; s < CH; s++)
                        ring[mid][c & 1][s][Nn] = (float)__ldg(mkp + t0 + s);
                }
                // numerator slices in the slack
#pragma unroll
                for (int rpt = 0; rpt < 3; rpt++) {
                    if (nt < Tn - 1) {
                        int tg0 = __ldg(tgp + nt), tg1 = __ldg(tgp + nt + 1);
                        int mk0 = __ldg(mkp + nt), mk1 = __ldg(mkp + nt + 1);
                        float ev = __ldg(inp + (size_t)nt * Nn + tg0);
                        tr_acc = fmaf(s_tr[tg0 * Nn + tg1], (float)mk1, tr_acc);
                        em_acc = fmaf(ev, (float)mk0, em_acc);
                        cnt += mk0;
                        nt += 32;
                    }
                }
                asm volatile("bar.sync %0, %1;" :: "r"(1 + mid), "r"(64));
            }
        }
        while (nt < Tn - 1) {
            int tg0 = __ldg(tgp + nt), tg1 = __ldg(tgp + nt + 1);
            int mk0 = __ldg(mkp + nt), mk1 = __ldg(mkp + nt + 1);
            float ev = __ldg(inp + (size_t)nt * Nn + tg0);
            tr_acc = fmaf(s_tr[tg0 * Nn + tg1], (float)mk1, tr_acc);
            em_acc = fmaf(ev, (float)mk0, em_acc);
            cnt += mk0;
            nt += 32;
        }
#pragma unroll
        for (int off = 16; off; off >>= 1) {
            tr_acc += __shfl_xor_sync(FULL, tr_acc, off);
            em_acc += __shfl_xor_sync(FULL, em_acc, off);
            cnt += __shfl_xor_sync(FULL, cnt, off);
        }
        if (j == 0) {
            int mkL = __ldg(mkp + Tn - 1);
            cnt += mkL;
            int li = cnt - 1; if (li < 0) li = 0;
            int tagL = __ldg(tgp + li);
            float evL = __ldg(inp + (size_t)(Tn - 1) * Nn + tagL) * (float)mkL;
            s_num = tr_acc + em_acc + evL;
        }
        __syncthreads();   // join
    }
}

extern "C" void kernel_launch(void* const* d_in, const int* in_sizes, int n_in,
                              void* d_out, int out_size) {
    const float* inputs     = (const float*)d_in[0];
    const int*   tags       = (const int*)d_in[1];
    const float* hiddens    = (const float*)d_in[2];
    const int*   mask       = (const int*)d_in[3];
    const float* p_in       = (const float*)d_in[4];
    const float* p_cross    = (const float*)d_in[5];
    const float* p_out      = (const float*)d_in[6];
    const float* p_to_out   = (const float*)d_in[7];
    const float* p_from_out = (const float*)d_in[8];
    const float* w_attn     = (const float*)d_in[9];
    const float* b_attn     = (const float*)d_in[10];

    k_build<<<1, 1024>>>(hiddens, p_in, p_cross, p_out, p_to_out, p_from_out,
                         w_attn, b_attn);
    k_scan<<<Bn, 160>>>(inputs, tags, mask, (float*)d_out);
}

// round 7
// speedup vs baseline: 1.4218x; 1.0352x over previous
#include <cuda_runtime.h>
#include <cstdint>
#include <cstddef>

#define Bn 256
#define Tn 2048
#define Nn 17
#define En 8
#define An 4
#define Mn 2
#define Hn 768
#define FULL 0xffffffffu

// segment lengths (balanced to measured rates):
// fwd vector: t = 0..LV-1, matrix B: t = LV..LV+LM-1,
// matrix C: t = LV+LM..LV+2LM-1, bwd vector: t = 2048-LV..2047.
#define LV 608
#define LM 416
#define CH 32            // ring chunk (steps)
#define NCH (LM / CH)    // 13

__device__ float g_trans[Nn * Nn];
__device__ float g_E[Nn * Nn];
__device__ float g_scratch[Bn];
__device__ int g_done;

// ---------------------------------------------------------------------------
// Kernel 1: build transition matrix (17x17) and its elementwise exp.
// ---------------------------------------------------------------------------
__global__ void k_build(const float* __restrict__ hiddens,
                        const float* __restrict__ p_in,
                        const float* __restrict__ p_cross,
                        const float* __restrict__ p_out,
                        const float* __restrict__ p_to_out,
                        const float* __restrict__ p_from_out,
                        const float* __restrict__ w_attn,
                        const float* __restrict__ b_attn) {
    __shared__ float att[En][An];
    int tid = threadIdx.x;
    int wid = tid >> 5, lane = tid & 31;
    if (tid == 0) g_done = 0;
    if (wid < En * An) {
        int e = wid / An, a = wid % An;
        float s = 0.f;
        for (int h = lane; h < Hn; h += 32)
            s = fmaf(hiddens[e * Hn + h], w_attn[h * An + a], s);
#pragma unroll
        for (int off = 16; off; off >>= 1) s += __shfl_xor_sync(FULL, s, off);
        if (lane == 0) att[e][a] = s + b_attn[a];
    }
    __syncthreads();
    if (tid < An) {
        int a = tid;
        float col[En], mx = -3.4e38f;
        for (int e = 0; e < En; e++) { col[e] = att[e][a]; mx = fmaxf(mx, col[e]); }
        float sm = 0.f;
        for (int e = 0; e < En; e++) { col[e] = expf(col[e] - mx); sm += col[e]; }
        for (int e = 0; e < En; e++) att[e][a] = col[e] / sm;
    }
    __syncthreads();
    if (tid < En) {
        int e = tid;
        float row[An], mx = -3.4e38f;
        for (int a = 0; a < An; a++) { row[a] = att[e][a] * 10.f; mx = fmaxf(mx, row[a]); }
        float sm = 0.f;
        for (int a = 0; a < An; a++) { row[a] = expf(row[a] - mx); sm += row[a]; }
        for (int a = 0; a < An; a++) att[e][a] = row[a] / sm;
    }
    __syncthreads();
    if (tid < Nn * Nn) {
        int r = tid / Nn, c = tid % Nn;
        float v;
        if (r == 0 && c == 0) {
            v = p_out[0];
        } else if (r == 0) {
            v = p_from_out[(c - 1) % Mn];
        } else if (c == 0) {
            v = p_to_out[(r - 1) % Mn];
        } else {
            int e = (r - 1) / Mn, m = (r - 1) % Mn;
            int f = (c - 1) / Mn, mp = (c - 1) % Mn;
            if (e == f) {
                float s2 = 0.f;
                for (int a = 0; a < An; a++)
                    s2 = fmaf(p_in[a * Mn * Mn + m * Mn + mp], att[e][a], s2);
                v = s2 * (1.0f / An);
            } else {
                v = p_cross[m * Mn + mp];
            }
        }
        g_trans[tid] = v;
        g_E[tid] = expf(v);
    }
}

// ---------------------------------------------------------------------------
// Kernel 2: 5 warps per batch, roles permuted per-block so co-resident blocks
// place issue-heavy matrix warps on different SMSPs:
//  role0: forward vector scan   role1: backward vector scan
//  role2/3: matrix segments B/C (column-per-lane, throughput-bound)
//  role4: producer (exp ring) + numerator
// ---------------------------------------------------------------------------
__global__ void __launch_bounds__(160, 2)
k_scan(const float* __restrict__ inputs,
       const int* __restrict__ tags,
       const int* __restrict__ mask,
       float* __restrict__ out) {
    int b = blockIdx.x;
    int wid = threadIdx.x >> 5;
    int j = threadIdx.x & 31;
    bool act = (j < Nn);
    // blocks >=148 share an SM with block (b-148); swap chain/matrix roles so
    // each SMSP gets one heavy + one light warp instead of two heavy.
    int role = (b >= 148 && wid < 4) ? (wid ^ 2) : wid;

    __shared__ float s_tr[Nn * Nn];
    __shared__ __align__(16) float wb[2][2][20];
    __shared__ __align__(16) float ring[2][2][CH][20];   // [mid][slot][step][state/mask]
    __shared__ __align__(16) float smM[2][Nn][20];       // matrix columns
    __shared__ double smL[2][Nn];                        // matrix column log2-scales
    __shared__ __align__(16) float sx[20], sy[20], sxs[20], szz[20], szs[20];
    __shared__ double s_l2b;
    __shared__ float s_num;

    for (int idx = threadIdx.x; idx < Nn * Nn; idx += 160) s_tr[idx] = g_trans[idx];
    __syncthreads();

    const float* inp = inputs + (size_t)b * Tn * Nn;
    const int* tgp = tags + (size_t)b * Tn;
    const int* mkp = mask + (size_t)b * Tn;

    if (role == 0) {
        // ===================== FORWARD: t in [0, LV) =====================
        float E0  = act ? g_E[0 * Nn + j]  : 0.f, E1  = act ? g_E[1 * Nn + j]  : 0.f;
        float E2  = act ? g_E[2 * Nn + j]  : 0.f, E3  = act ? g_E[3 * Nn + j]  : 0.f;
        float E4  = act ? g_E[4 * Nn + j]  : 0.f, E5  = act ? g_E[5 * Nn + j]  : 0.f;
        float E6  = act ? g_E[6 * Nn + j]  : 0.f, E7  = act ? g_E[7 * Nn + j]  : 0.f;
        float E8  = act ? g_E[8 * Nn + j]  : 0.f, E9  = act ? g_E[9 * Nn + j]  : 0.f;
        float E10 = act ? g_E[10 * Nn + j] : 0.f, E11 = act ? g_E[11 * Nn + j] : 0.f;
        float E12 = act ? g_E[12 * Nn + j] : 0.f, E13 = act ? g_E[13 * Nn + j] : 0.f;
        float E14 = act ? g_E[14 * Nn + j] : 0.f, E15 = act ? g_E[15 * Nn + j] : 0.f;
        float E16 = act ? g_E[16 * Nn + j] : 0.f;

        float rA[8], rB[8], rC[8];
        int mA[8], mB[8], mC[8];
        float ew[8];
#pragma unroll
        for (int u = 0; u < 8; u++) {
            rA[u] = act ? __ldg(inp + (size_t)u * Nn + j) : 0.f;
            mA[u] = __ldg(mkp + u);
            rB[u] = act ? __ldg(inp + (size_t)(8 + u) * Nn + j) : 0.f;
            mB[u] = __ldg(mkp + 8 + u);
            rC[u] = 0.f; mC[u] = 0;
        }
#pragma unroll
        for (int u = 0; u < 8; u++) ew[u] = __expf(rA[u]);

        float r0v = rA[0];
        float s0 = __shfl_sync(FULL, r0v, 0);
        float w = act ? __expf(r0v - s0) : 0.f;
        double l2 = 0.0;
        if (act) wb[0][0][j] = w;

        for (int blk = 0; blk < LV / 8; blk++) {
            if (blk + 2 < LV / 8) {
                int tp = (blk + 2) * 8;
#pragma unroll
                for (int u = 0; u < 8; u++) {
                    rC[u] = act ? __ldg(inp + (size_t)(tp + u) * Nn + j) : 0.f;
                    mC[u] = __ldg(mkp + tp + u);
                }
            }
#pragma unroll
            for (int u = 0; u < 8; u++) {
                if (blk == 0 && u == 0) continue;
                __syncwarp();
                float4 v0 = *(const float4*)&wb[0][(u + 1) & 1][0];
                float4 v1 = *(const float4*)&wb[0][(u + 1) & 1][4];
                float4 v2 = *(const float4*)&wb[0][(u + 1) & 1][8];
                float4 v3 = *(const float4*)&wb[0][(u + 1) & 1][12];
                float v16 = wb[0][(u + 1) & 1][16];
                float a0 = v0.x * E0, a1 = v0.y * E1, a2 = v0.z * E2, a3 = v0.w * E3;
                float a4 = v1.x * E4, a5 = v1.y * E5, a6 = v1.z * E6, a7 = v1.w * E7;
                a0 = fmaf(v2.x, E8, a0);  a1 = fmaf(v2.y, E9, a1);
                a2 = fmaf(v2.z, E10, a2); a3 = fmaf(v2.w, E11, a3);
                a4 = fmaf(v3.x, E12, a4); a5 = fmaf(v3.y, E13, a5);
                a6 = fmaf(v3.z, E14, a6); a7 = fmaf(v3.w, E15, a7);
                a0 = fmaf(v16, E16, a0);
                float wn = ew[u] * (((a0 + a1) + (a2 + a3)) + ((a4 + a5) + (a6 + a7)));
                w = (mA[u] > 0) ? wn : w;
                if (u == 7) {
                    float sc = v0.x;
                    w *= __frcp_rn(sc);
                    l2 += (double)__log2f(sc);
                }
                if (act) wb[0][u & 1][j] = w;
            }
#pragma unroll
            for (int u = 0; u < 8; u++) {
                ew[u] = __expf(rB[u]);
                rA[u] = rB[u]; mA[u] = mB[u];
                rB[u] = rC[u]; mB[u] = mC[u];
            }
        }
        if (act) sx[j] = w;
        __syncthreads();   // join

        // ---- combine: den = s0 + ln2*(l2f + l2b + maxB + maxC) + ln(y.(C.(B.x))) ----
        double maxB = -1e300, maxC = -1e300;
#pragma unroll
        for (int k = 0; k < Nn; k++) {
            double vB = smL[0][k], vC = smL[1][k];
            maxB = vB > maxB ? vB : maxB;
            maxC = vC > maxC ? vC : maxC;
        }
        if (act) sxs[j] = sx[j] * exp2f((float)(smL[0][j] - maxB));
        __syncwarp();
        float z = 0.f;
        if (act) {
#pragma unroll
            for (int k = 0; k < Nn; k++) z = fmaf(smM[0][k][j], sxs[k], z);
            szz[j] = z;
        }
        __syncwarp();
        if (act) szs[j] = szz[j] * exp2f((float)(smL[1][j] - maxC));
        __syncwarp();
        float z2 = 0.f;
        if (act) {
#pragma unroll
            for (int k = 0; k < Nn; k++) z2 = fmaf(smM[1][k][j], szs[k], z2);
        }
        float prod = act ? sy[j] * z2 : 0.f;
#pragma unroll
        for (int off = 16; off; off >>= 1) prod += __shfl_xor_sync(FULL, prod, off);
        if (j == 0) {
            double den = (double)s0
                       + 0.6931471805599453 * (l2 + s_l2b + maxB + maxC)
                       + log((double)prod);
            g_scratch[b] = (float)((double)s_num - den);
            __threadfence();
        }
        int flag = 0;
        if (j == 0) {
            int ticket = atomicAdd(&g_done, 1);
            flag = (ticket == Bn - 1);
        }
        flag = __shfl_sync(FULL, flag, 0);
        if (flag) {
            __threadfence();
            volatile float* gs = g_scratch;
            double acc = 0.0;
#pragma unroll
            for (int k = 0; k < Bn / 32; k++) acc += (double)gs[j + k * 32];
#pragma unroll
            for (int off = 16; off; off >>= 1) acc += __shfl_xor_sync(FULL, acc, off);
            if (j == 0) out[0] = (float)acc;
        }
    } else if (role == 1) {
        // ===================== BACKWARD: t in [2048-LV, 2048) =====================
        float F0  = act ? g_E[j * Nn + 0]  : 0.f, F1  = act ? g_E[j * Nn + 1]  : 0.f;
        float F2  = act ? g_E[j * Nn + 2]  : 0.f, F3  = act ? g_E[j * Nn + 3]  : 0.f;
        float F4  = act ? g_E[j * Nn + 4]  : 0.f, F5  = act ? g_E[j * Nn + 5]  : 0.f;
        float F6  = act ? g_E[j * Nn + 6]  : 0.f, F7  = act ? g_E[j * Nn + 7]  : 0.f;
        float F8  = act ? g_E[j * Nn + 8]  : 0.f, F9  = act ? g_E[j * Nn + 9]  : 0.f;
        float F10 = act ? g_E[j * Nn + 10] : 0.f, F11 = act ? g_E[j * Nn + 11] : 0.f;
        float F12 = act ? g_E[j * Nn + 12] : 0.f, F13 = act ? g_E[j * Nn + 13] : 0.f;
        float F14 = act ? g_E[j * Nn + 14] : 0.f, F15 = act ? g_E[j * Nn + 15] : 0.f;
        float F16 = act ? g_E[j * Nn + 16] : 0.f;

        float rA[8], rB[8], rC[8];
        int mA[8], mB[8], mC[8];
        float ew[8];
#pragma unroll
        for (int u = 0; u < 8; u++) {
            rA[u] = act ? __ldg(inp + (size_t)(2040 + u) * Nn + j) : 0.f;
            mA[u] = __ldg(mkp + 2040 + u);
            rB[u] = act ? __ldg(inp + (size_t)(2032 + u) * Nn + j) : 0.f;
            mB[u] = __ldg(mkp + 2032 + u);
            rC[u] = 0.f; mC[u] = 0;
        }
#pragma unroll
        for (int u = 0; u < 8; u++) ew[u] = __expf(rA[u]);

        float ur = 1.0f;
        double l2 = 0.0;

        for (int tb = 2040; tb >= Tn - LV; tb -= 8) {
            if (tb - 16 >= Tn - LV) {
                int tp = tb - 16;
#pragma unroll
                for (int u = 0; u < 8; u++) {
                    rC[u] = act ? __ldg(inp + (size_t)(tp + u) * Nn + j) : 0.f;
                    mC[u] = __ldg(mkp + tp + u);
                }
            }
#pragma unroll
            for (int u = 7; u >= 0; u--) {
                float z = ew[u] * ur;
                if (act) wb[1][u & 1][j] = z;
                __syncwarp();
                float4 v0 = *(const float4*)&wb[1][u & 1][0];
                float4 v1 = *(const float4*)&wb[1][u & 1][4];
                float4 v2 = *(const float4*)&wb[1][u & 1][8];
                float4 v3 = *(const float4*)&wb[1][u & 1][12];
                float v16 = wb[1][u & 1][16];
                float a0 = v0.x * F0, a1 = v0.y * F1, a2 = v0.z * F2, a3 = v0.w * F3;
                float a4 = v1.x * F4, a5 = v1.y * F5, a6 = v1.z * F6, a7 = v1.w * F7;
                a0 = fmaf(v2.x, F8, a0);  a1 = fmaf(v2.y, F9, a1);
                a2 = fmaf(v2.z, F10, a2); a3 = fmaf(v2.w, F11, a3);
                a4 = fmaf(v3.x, F12, a4); a5 = fmaf(v3.y, F13, a5);
                a6 = fmaf(v3.z, F14, a6); a7 = fmaf(v3.w, F15, a7);
                a0 = fmaf(v16, F16, a0);
                float cand = ((a0 + a1) + (a2 + a3)) + ((a4 + a5) + (a6 + a7));
                ur = (mA[u] > 0) ? cand : ur;
                if (u == 0) {
                    float sc = v0.x;
                    ur *= __frcp_rn(sc);
                    l2 += (double)__log2f(sc);
                }
            }
#pragma unroll
            for (int u = 0; u < 8; u++) {
                ew[u] = __expf(rB[u]);
                rA[u] = rB[u]; mA[u] = mB[u];
                rB[u] = rC[u]; mB[u] = mC[u];
            }
        }
        if (act) sy[j] = ur;
        if (j == 0) s_l2b = l2;
        __syncthreads();   // join
    } else if (role == 2 || role == 3) {
        // ===================== MATRIX segment (column per lane) =====================
        int mid = role - 2;
        float EO = g_E[0], FO0 = g_E[1], FO1 = g_E[2];
        float TO0 = g_E[Nn], TO1 = g_E[2 * Nn];
        float C00 = g_E[1 * Nn + 3], C01 = g_E[1 * Nn + 4];
        float C10 = g_E[2 * Nn + 3], C11 = g_E[2 * Nn + 4];
        float D00[8], D01[8], D10[8], D11[8];
#pragma unroll
        for (int f = 0; f < 8; f++) {
            int r0 = (1 + 2 * f) * Nn, r1 = (2 + 2 * f) * Nn;
            int c0 = 1 + 2 * f, c1 = 2 + 2 * f;
            D00[f] = g_E[r0 + c0] - C00;
            D01[f] = g_E[r0 + c1] - C01;
            D10[f] = g_E[r1 + c0] - C10;
            D11[f] = g_E[r1 + c1] - C11;
        }
        float bb[17];
#pragma unroll
        for (int i = 0; i < 17; i++) bb[i] = (i == j) ? 1.f : 0.f;
        double l2 = 0.0;
        int scount = 0;

        for (int c = 0; c < NCH; c++) {
            asm volatile("bar.sync %0, %1;" :: "r"(1 + mid), "r"(64));
            const float* rbase = &ring[mid][c & 1][0][0];
#pragma unroll 4
            for (int s = 0; s < CH; s++) {
                const float* rw = rbase + s * 20;
                float4 e0 = *(const float4*)(rw + 0);
                float4 e1 = *(const float4*)(rw + 4);
                float4 e2 = *(const float4*)(rw + 8);
                float4 e3 = *(const float4*)(rw + 12);
                float2 et = *(const float2*)(rw + 16);
                float ee[17] = {e0.x, e0.y, e0.z, e0.w, e1.x, e1.y, e1.z, e1.w,
                                e2.x, e2.y, e2.z, e2.w, e3.x, e3.y, e3.z, e3.w, et.x};
                if (et.y > 0.f) {
                    float S0 = ((bb[1] + bb[3]) + (bb[5] + bb[7]))
                             + ((bb[9] + bb[11]) + (bb[13] + bb[15]));
                    float S1 = ((bb[2] + bb[4]) + (bb[6] + bb[8]))
                             + ((bb[10] + bb[12]) + (bb[14] + bb[16]));
                    float U0 = fmaf(C10, S1, C00 * S0);
                    float U1 = fmaf(C11, S1, C01 * S0);
                    float V0 = fmaf(FO0, bb[0], U0);
                    float V1 = fmaf(FO1, bb[0], U1);
                    float nb0 = fmaf(TO1, S1, fmaf(TO0, S0, EO * bb[0]));
                    bb[0] = ee[0] * nb0;
#pragma unroll
                    for (int f = 0; f < 8; f++) {
                        float bm0 = bb[1 + 2 * f], bm1 = bb[2 + 2 * f];
                        float t0 = fmaf(D10[f], bm1, fmaf(D00[f], bm0, V0));
                        float t1 = fmaf(D11[f], bm1, fmaf(D01[f], bm0, V1));
                        bb[1 + 2 * f] = ee[1 + 2 * f] * t0;
                        bb[2 + 2 * f] = ee[2 + 2 * f] * t1;
                    }
                }
                if ((++scount & 7) == 0) {
                    float sc = bb[0];
                    if (sc > 0.f) {
                        float iv = __frcp_rn(sc);
                        l2 += (double)__log2f(sc);
#pragma unroll
                        for (int i = 0; i < 17; i++) bb[i] *= iv;
                    }
                }
            }
        }
        if (act) {
#pragma unroll
            for (int i = 0; i < 17; i++) smM[mid][j][i] = bb[i];
            smL[mid][j] = l2;
        }
        __syncthreads();   // join
    } else {
        // ===================== PRODUCER + NUMERATOR =====================
        float tr_acc = 0.f, em_acc = 0.f;
        int cnt = 0;
        int nt = j;
        for (int c = 0; c < NCH; c++) {
#pragma unroll
            for (int mid = 0; mid < 2; mid++) {
                int t0 = LV + mid * LM + c * CH;
                if (j < Nn) {
#pragma unroll 8
                    for (int s = 0; s < CH; s++)
                        ring[mid][c & 1][s][j] =
                            __expf(__ldg(inp + (size_t)(t0 + s) * Nn + j));
                } else if (j == Nn) {
#pragma unroll 8
                    for (int s = 0; s < CH; s++)
                        ring[mid][c & 1][s][Nn] = (float)__ldg(mkp + t0 + s);
                }
#pragma unroll
                for (int rpt = 0; rpt < 3; rpt++) {
                    if (nt < Tn - 1) {
                        int tg0 = __ldg(tgp + nt), tg1 = __ldg(tgp + nt + 1);
                        int mk0 = __ldg(mkp + nt), mk1 = __ldg(mkp + nt + 1);
                        float ev = __ldg(inp + (size_t)nt * Nn + tg0);
                        tr_acc = fmaf(s_tr[tg0 * Nn + tg1], (float)mk1, tr_acc);
                        em_acc = fmaf(ev, (float)mk0, em_acc);
                        cnt += mk0;
                        nt += 32;
                    }
                }
                asm volatile("bar.sync %0, %1;" :: "r"(1 + mid), "r"(64));
            }
        }
        while (nt < Tn - 1) {
            int tg0 = __ldg(tgp + nt), tg1 = __ldg(tgp + nt + 1);
            int mk0 = __ldg(mkp + nt), mk1 = __ldg(mkp + nt + 1);
            float ev = __ldg(inp + (size_t)nt * Nn + tg0);
            tr_acc = fmaf(s_tr[tg0 * Nn + tg1], (float)mk1, tr_acc);
            em_acc = fmaf(ev, (float)mk0, em_acc);
            cnt += mk0;
            nt += 32;
        }
#pragma unroll
        for (int off = 16; off; off >>= 1) {
            tr_acc += __shfl_xor_sync(FULL, tr_acc, off);
            em_acc += __shfl_xor_sync(FULL, em_acc, off);
            cnt += __shfl_xor_sync(FULL, cnt, off);
        }
        if (j == 0) {
            int mkL = __ldg(mkp + Tn - 1);
            cnt += mkL;
            int li = cnt - 1; if (li < 0) li = 0;
            int tagL = __ldg(tgp + li);
            float evL = __ldg(inp + (size_t)(Tn - 1) * Nn + tagL) * (float)mkL;
            s_num = tr_acc + em_acc + evL;
        }
        __syncthreads();   // join
    }
}

extern "C" void kernel_launch(void* const* d_in, const int* in_sizes, int n_in,
                              void* d_out, int out_size) {
    const float* inputs     = (const float*)d_in[0];
    const int*   tags       = (const int*)d_in[1];
    const float* hiddens    = (const float*)d_in[2];
    const int*   mask       = (const int*)d_in[3];
    const float* p_in       = (const float*)d_in[4];
    const float* p_cross    = (const float*)d_in[5];
    const float* p_out      = (const float*)d_in[6];
    const float* p_to_out   = (const float*)d_in[7];
    const float* p_from_out = (const float*)d_in[8];
    const float* w_attn     = (const float*)d_in[9];
    const float* b_attn     = (const float*)d_in[10];

    k_build<<<1, 1024>>>(hiddens, p_in, p_cross, p_out, p_to_out, p_from_out,
                         w_attn, b_attn);
    k_scan<<<Bn, 160>>>(inputs, tags, mask, (float*)d_out);
}

// round 9
// speedup vs baseline: 1.7034x; 1.1980x over previous
#include <cuda_runtime.h>
#include <cstdint>
#include <cstddef>

#define Bn 256
#define Tn 2048
#define Nn 17
#define En 8
#define An 4
#define Mn 2
#define Hn 768
#define FULL 0xffffffffu
#define SEG 408   // segments: [0..407][408..815][816..1223][1224..1631][1632..2047]

__device__ float g_trans[Nn * Nn];
__device__ float g_E[Nn * Nn];
__device__ float g_scratch[Bn];
__device__ int g_done;

// ---------------------------------------------------------------------------
// Kernel 1: build transition matrix (17x17) and its elementwise exp.
// ---------------------------------------------------------------------------
__global__ void k_build(const float* __restrict__ hiddens,
                        const float* __restrict__ p_in,
                        const float* __restrict__ p_cross,
                        const float* __restrict__ p_out,
                        const float* __restrict__ p_to_out,
                        const float* __restrict__ p_from_out,
                        const float* __restrict__ w_attn,
                        const float* __restrict__ b_attn) {
    __shared__ float att[En][An];
    int tid = threadIdx.x;
    int wid = tid >> 5, lane = tid & 31;
    if (tid == 0) g_done = 0;
    if (wid < En * An) {
        int e = wid / An, a = wid % An;
        float s = 0.f;
        for (int h = lane; h < Hn; h += 32)
            s = fmaf(hiddens[e * Hn + h], w_attn[h * An + a], s);
#pragma unroll
        for (int off = 16; off; off >>= 1) s += __shfl_xor_sync(FULL, s, off);
        if (lane == 0) att[e][a] = s + b_attn[a];
    }
    __syncthreads();
    if (tid < An) {
        int a = tid;
        float col[En], mx = -3.4e38f;
        for (int e = 0; e < En; e++) { col[e] = att[e][a]; mx = fmaxf(mx, col[e]); }
        float sm = 0.f;
        for (int e = 0; e < En; e++) { col[e] = expf(col[e] - mx); sm += col[e]; }
        for (int e = 0; e < En; e++) att[e][a] = col[e] / sm;
    }
    __syncthreads();
    if (tid < En) {
        int e = tid;
        float row[An], mx = -3.4e38f;
        for (int a = 0; a < An; a++) { row[a] = att[e][a] * 10.f; mx = fmaxf(mx, row[a]); }
        float sm = 0.f;
        for (int a = 0; a < An; a++) { row[a] = expf(row[a] - mx); sm += row[a]; }
        for (int a = 0; a < An; a++) att[e][a] = row[a] / sm;
    }
    __syncthreads();
    if (tid < Nn * Nn) {
        int r = tid / Nn, c = tid % Nn;
        float v;
        if (r == 0 && c == 0) {
            v = p_out[0];
        } else if (r == 0) {
            v = p_from_out[(c - 1) % Mn];
        } else if (c == 0) {
            v = p_to_out[(r - 1) % Mn];
        } else {
            int e = (r - 1) / Mn, m = (r - 1) % Mn;
            int f = (c - 1) / Mn, mp = (c - 1) % Mn;
            if (e == f) {
                float s2 = 0.f;
                for (int a = 0; a < An; a++)
                    s2 = fmaf(p_in[a * Mn * Mn + m * Mn + mp], att[e][a], s2);
                v = s2 * (1.0f / An);
            } else {
                v = p_cross[m * Mn + mp];
            }
        }
        g_trans[tid] = v;
        g_E[tid] = expf(v);
    }
}

// ---------------------------------------------------------------------------
// Kernel 2: 9 warps per batch, 5 time-segments, rank-1 interior summaries.
//  warps 0-3: forward chains a_s over segments 1..4 (w0 from true alpha0,
//             w1-3 probe from ones); warps 4-7: backward chains b_s over
//             segments 2..5 from ones; warp 8: numerator.
// den = s0 + ln2*(La1+Lb2+Lb3+Lb4+Lb5)
//       + sum_s ln(b_{s+1}.a_s) - sum_{s=2..4} ln(sum a_s).
// (rank-1: M_s ~ a_s b_s^T / sum(a_s); product of ~408 positive matrices is
//  numerically rank-1 by Hilbert-metric contraction.)
// ---------------------------------------------------------------------------
__global__ void __launch_bounds__(288, 2)
k_scan(const float* __restrict__ inputs,
       const int* __restrict__ tags,
       const int* __restrict__ mask,
       float* __restrict__ out) {
    int b = blockIdx.x;
    int wid = threadIdx.x >> 5;
    int j = threadIdx.x & 31;
    bool act = (j < Nn);

    __shared__ float s_tr[Nn * Nn];
    __shared__ __align__(16) float wb[8][2][20];
    __shared__ __align__(16) float s_vec[8][20];
    __shared__ double s_l2[8];
    __shared__ float s_s0, s_num;

    for (int idx = threadIdx.x; idx < Nn * Nn; idx += 288) s_tr[idx] = g_trans[idx];
    __syncthreads();

    const float* inp = inputs + (size_t)b * Tn * Nn;
    const int* tgp = tags + (size_t)b * Tn;
    const int* mkp = mask + (size_t)b * Tn;

    if (wid < 4) {
        // ============ FORWARD chain cw: t = tb0 .. tb0+407 ============
        int cw = wid;
        int tb0 = cw * SEG;
        float E0  = act ? g_E[0 * Nn + j]  : 0.f, E1  = act ? g_E[1 * Nn + j]  : 0.f;
        float E2  = act ? g_E[2 * Nn + j]  : 0.f, E3  = act ? g_E[3 * Nn + j]  : 0.f;
        float E4  = act ? g_E[4 * Nn + j]  : 0.f, E5  = act ? g_E[5 * Nn + j]  : 0.f;
        float E6  = act ? g_E[6 * Nn + j]  : 0.f, E7  = act ? g_E[7 * Nn + j]  : 0.f;
        float E8  = act ? g_E[8 * Nn + j]  : 0.f, E9  = act ? g_E[9 * Nn + j]  : 0.f;
        float E10 = act ? g_E[10 * Nn + j] : 0.f, E11 = act ? g_E[11 * Nn + j] : 0.f;
        float E12 = act ? g_E[12 * Nn + j] : 0.f, E13 = act ? g_E[13 * Nn + j] : 0.f;
        float E14 = act ? g_E[14 * Nn + j] : 0.f, E15 = act ? g_E[15 * Nn + j] : 0.f;
        float E16 = act ? g_E[16 * Nn + j] : 0.f;

        float rA[8], rB[8], rC[8];
        int mA[8], mB[8], mC[8];
        float ew[8];
#pragma unroll
        for (int u = 0; u < 8; u++) {
            rA[u] = act ? __ldg(inp + (size_t)(tb0 + u) * Nn + j) : 0.f;
            mA[u] = __ldg(mkp + tb0 + u);
            rB[u] = act ? __ldg(inp + (size_t)(tb0 + 8 + u) * Nn + j) : 0.f;
            mB[u] = __ldg(mkp + tb0 + 8 + u);
            rC[u] = 0.f; mC[u] = 0;
        }
#pragma unroll
        for (int u = 0; u < 8; u++) ew[u] = __expf(rA[u]);

        float w;
        float s0 = 0.f;
        double l2 = 0.0;
        if (cw == 0) {      // true init: alpha0 = emit(t=0)
            float r0v = rA[0];
            s0 = __shfl_sync(FULL, r0v, 0);
            w = act ? __expf(r0v - s0) : 0.f;
        } else {            // rank-1 probe from ones
            w = act ? 1.f : 0.f;
        }
        // init BOTH ping-pong slots: step u reads slot (u+1)&1, so the first
        // executed step (u=0 for cw>=1, u=1 for cw==0) needs its slot valid.
        if (act) { wb[cw][0][j] = w; wb[cw][1][j] = w; }

        for (int blk = 0; blk < SEG / 8; blk++) {
            if (blk + 2 < SEG / 8) {
                int tp = tb0 + (blk + 2) * 8;
#pragma unroll
                for (int u = 0; u < 8; u++) {
                    rC[u] = act ? __ldg(inp + (size_t)(tp + u) * Nn + j) : 0.f;
                    mC[u] = __ldg(mkp + tp + u);
                }
            }
#pragma unroll
            for (int u = 0; u < 8; u++) {
                if (cw == 0 && blk == 0 && u == 0) continue;   // t=0 in init
                __syncwarp();
                float4 v0 = *(const float4*)&wb[cw][(u + 1) & 1][0];
                float4 v1 = *(const float4*)&wb[cw][(u + 1) & 1][4];
                float4 v2 = *(const float4*)&wb[cw][(u + 1) & 1][8];
                float4 v3 = *(const float4*)&wb[cw][(u + 1) & 1][12];
                float v16 = wb[cw][(u + 1) & 1][16];
                float a0 = v0.x * E0, a1 = v0.y * E1, a2 = v0.z * E2, a3 = v0.w * E3;
                float a4 = v1.x * E4, a5 = v1.y * E5, a6 = v1.z * E6, a7 = v1.w * E7;
                a0 = fmaf(v2.x, E8, a0);  a1 = fmaf(v2.y, E9, a1);
                a2 = fmaf(v2.z, E10, a2); a3 = fmaf(v2.w, E11, a3);
                a4 = fmaf(v3.x, E12, a4); a5 = fmaf(v3.y, E13, a5);
                a6 = fmaf(v3.z, E14, a6); a7 = fmaf(v3.w, E15, a7);
                a0 = fmaf(v16, E16, a0);
                float wn = ew[u] * (((a0 + a1) + (a2 + a3)) + ((a4 + a5) + (a6 + a7)));
                w = (mA[u] > 0) ? wn : w;
                if (u == 7) {            // free renorm via prev w[0]
                    float sc = v0.x;
                    w *= __frcp_rn(sc);
                    l2 += (double)__log2f(sc);
                }
                if (act) wb[cw][u & 1][j] = w;
            }
#pragma unroll
            for (int u = 0; u < 8; u++) {
                ew[u] = __expf(rB[u]);
                rA[u] = rB[u]; mA[u] = mB[u];
                rB[u] = rC[u]; mB[u] = mC[u];
            }
        }
        if (act) s_vec[cw][j] = w;
        if (j == 0) { s_l2[cw] = l2; if (cw == 0) s_s0 = s0; }
    } else if (wid < 8) {
        // ============ BACKWARD chain cw over segment cw+2 ============
        int cw = wid - 4;
        int NB = (cw == 3) ? 52 : 51;
        int thi = (cw == 3) ? 2047 : (815 + cw * SEG);
        int tbA = thi - 7;
        int tlo = thi - NB * 8 + 1;
        float F0  = act ? g_E[j * Nn + 0]  : 0.f, F1  = act ? g_E[j * Nn + 1]  : 0.f;
        float F2  = act ? g_E[j * Nn + 2]  : 0.f, F3  = act ? g_E[j * Nn + 3]  : 0.f;
        float F4  = act ? g_E[j * Nn + 4]  : 0.f, F5  = act ? g_E[j * Nn + 5]  : 0.f;
        float F6  = act ? g_E[j * Nn + 6]  : 0.f, F7  = act ? g_E[j * Nn + 7]  : 0.f;
        float F8  = act ? g_E[j * Nn + 8]  : 0.f, F9  = act ? g_E[j * Nn + 9]  : 0.f;
        float F10 = act ? g_E[j * Nn + 10] : 0.f, F11 = act ? g_E[j * Nn + 11] : 0.f;
        float F12 = act ? g_E[j * Nn + 12] : 0.f, F13 = act ? g_E[j * Nn + 13] : 0.f;
        float F14 = act ? g_E[j * Nn + 14] : 0.f, F15 = act ? g_E[j * Nn + 15] : 0.f;
        float F16 = act ? g_E[j * Nn + 16] : 0.f;

        float rA[8], rB[8], rC[8];
        int mA[8], mB[8], mC[8];
        float ew[8];
#pragma unroll
        for (int u = 0; u < 8; u++) {
            rA[u] = act ? __ldg(inp + (size_t)(tbA + u) * Nn + j) : 0.f;
            mA[u] = __ldg(mkp + tbA + u);
            rB[u] = act ? __ldg(inp + (size_t)(tbA - 8 + u) * Nn + j) : 0.f;
            mB[u] = __ldg(mkp + tbA - 8 + u);
            rC[u] = 0.f; mC[u] = 0;
        }
#pragma unroll
        for (int u = 0; u < 8; u++) ew[u] = __expf(rA[u]);

        float ur = act ? 1.f : 0.f;
        double l2 = 0.0;

        for (int tb = tbA; tb >= tlo; tb -= 8) {
            if (tb - 16 >= tlo) {
                int tp = tb - 16;
#pragma unroll
                for (int u = 0; u < 8; u++) {
                    rC[u] = act ? __ldg(inp + (size_t)(tp + u) * Nn + j) : 0.f;
                    mC[u] = __ldg(mkp + tp + u);
                }
            }
#pragma unroll
            for (int u = 7; u >= 0; u--) {
                float z = ew[u] * ur;
                if (act) wb[4 + cw][u & 1][j] = z;
                __syncwarp();
                float4 v0 = *(const float4*)&wb[4 + cw][u & 1][0];
                float4 v1 = *(const float4*)&wb[4 + cw][u & 1][4];
                float4 v2 = *(const float4*)&wb[4 + cw][u & 1][8];
                float4 v3 = *(const float4*)&wb[4 + cw][u & 1][12];
                float v16 = wb[4 + cw][u & 1][16];
                float a0 = v0.x * F0, a1 = v0.y * F1, a2 = v0.z * F2, a3 = v0.w * F3;
                float a4 = v1.x * F4, a5 = v1.y * F5, a6 = v1.z * F6, a7 = v1.w * F7;
                a0 = fmaf(v2.x, F8, a0);  a1 = fmaf(v2.y, F9, a1);
                a2 = fmaf(v2.z, F10, a2); a3 = fmaf(v2.w, F11, a3);
                a4 = fmaf(v3.x, F12, a4); a5 = fmaf(v3.y, F13, a5);
                a6 = fmaf(v3.z, F14, a6); a7 = fmaf(v3.w, F15, a7);
                a0 = fmaf(v16, F16, a0);
                float cand = ((a0 + a1) + (a2 + a3)) + ((a4 + a5) + (a6 + a7));
                ur = (mA[u] > 0) ? cand : ur;
                if (u == 0) {
                    float sc = v0.x;
                    ur *= __frcp_rn(sc);
                    l2 += (double)__log2f(sc);
                }
            }
#pragma unroll
            for (int u = 0; u < 8; u++) {
                ew[u] = __expf(rB[u]);
                rA[u] = rB[u]; mA[u] = mB[u];
                rB[u] = rC[u]; mB[u] = mC[u];
            }
        }
        if (act) s_vec[4 + cw][j] = ur;
        if (j == 0) s_l2[4 + cw] = l2;
    } else {
        // ===================== NUMERATOR =====================
        float tr_acc = 0.f, em_acc = 0.f;
        int cnt = 0;
        for (int t = j; t < Tn - 1; t += 32) {
            int tg0 = __ldg(tgp + t), tg1 = __ldg(tgp + t + 1);
            int mk0 = __ldg(mkp + t), mk1 = __ldg(mkp + t + 1);
            float ev = __ldg(inp + (size_t)t * Nn + tg0);
            tr_acc = fmaf(s_tr[tg0 * Nn + tg1], (float)mk1, tr_acc);
            em_acc = fmaf(ev, (float)mk0, em_acc);
            cnt += mk0;
        }
#pragma unroll
        for (int off = 16; off; off >>= 1) {
            tr_acc += __shfl_xor_sync(FULL, tr_acc, off);
            em_acc += __shfl_xor_sync(FULL, em_acc, off);
            cnt += __shfl_xor_sync(FULL, cnt, off);
        }
        if (j == 0) {
            int mkL = __ldg(mkp + Tn - 1);
            cnt += mkL;
            int li = cnt - 1; if (li < 0) li = 0;
            int tagL = __ldg(tgp + li);
            float evL = __ldg(inp + (size_t)(Tn - 1) * Nn + tagL) * (float)mkL;
            s_num = tr_acc + em_acc + evL;
        }
    }
    __syncthreads();

    if (wid == 0) {
        // ---- combine: telescoped rank-1 product ----
        float d1 = act ? s_vec[4][j] * s_vec[0][j] : 0.f;   // b2.a1
        float d2 = act ? s_vec[5][j] * s_vec[1][j] : 0.f;   // b3.a2
        float d3 = act ? s_vec[6][j] * s_vec[2][j] : 0.f;   // b4.a3
        float d4 = act ? s_vec[7][j] * s_vec[3][j] : 0.f;   // b5.a4
        float m2 = act ? s_vec[1][j] : 0.f;                  // sum a2
        float m3 = act ? s_vec[2][j] : 0.f;
        float m4 = act ? s_vec[3][j] : 0.f;
#pragma unroll
        for (int off = 16; off; off >>= 1) {
            d1 += __shfl_xor_sync(FULL, d1, off);
            d2 += __shfl_xor_sync(FULL, d2, off);
            d3 += __shfl_xor_sync(FULL, d3, off);
            d4 += __shfl_xor_sync(FULL, d4, off);
            m2 += __shfl_xor_sync(FULL, m2, off);
            m3 += __shfl_xor_sync(FULL, m3, off);
            m4 += __shfl_xor_sync(FULL, m4, off);
        }
        if (j == 0) {
            // scales of a2,a3,a4 cancel between d_s and m_s; only La1 and the
            // backward scales survive.
            double l2t = s_l2[0] + s_l2[4] + s_l2[5] + s_l2[6] + s_l2[7];
            double den = (double)s_s0 + 0.6931471805599453 * l2t
                       + log((double)d1) + log((double)d2)
                       + log((double)d3) + log((double)d4)
                       - log((double)m2) - log((double)m3) - log((double)m4);
            g_scratch[b] = (float)((double)s_num - den);
            __threadfence();
        }
        int flag = 0;
        if (j == 0) {
            int ticket = atomicAdd(&g_done, 1);
            flag = (ticket == Bn - 1);
        }
        flag = __shfl_sync(FULL, flag, 0);
        if (flag) {
            __threadfence();
            volatile float* gs = g_scratch;
            double acc = 0.0;
#pragma unroll
            for (int k = 0; k < Bn / 32; k++) acc += (double)gs[j + k * 32];
#pragma unroll
            for (int off = 16; off; off >>= 1) acc += __shfl_xor_sync(FULL, acc, off);
            if (j == 0) out[0] = (float)acc;
        }
    }
}

extern "C" void kernel_launch(void* const* d_in, const int* in_sizes, int n_in,
                              void* d_out, int out_size) {
    const float* inputs     = (const float*)d_in[0];
    const int*   tags       = (const int*)d_in[1];
    const float* hiddens    = (const float*)d_in[2];
    const int*   mask       = (const int*)d_in[3];
    const float* p_in       = (const float*)d_in[4];
    const float* p_cross    = (const float*)d_in[5];
    const float* p_out      = (const float*)d_in[6];
    const float* p_to_out   = (const float*)d_in[7];
    const float* p_from_out = (const float*)d_in[8];
    const float* w_attn     = (const float*)d_in[9];
    const float* b_attn     = (const float*)d_in[10];

    k_build<<<1, 1024>>>(hiddens, p_in, p_cross, p_out, p_to_out, p_from_out,
                         w_attn, b_attn);
    k_scan<<<Bn, 288>>>(inputs, tags, mask, (float*)d_out);
}